// round 11
// baseline (speedup 1.0000x reference)
#include <cuda_runtime.h>
#include <cuda_bf16.h>
#include <cuda_fp16.h>
#include <math.h>
#include <stdint.h>

#define BB 2
#define LL 2048
#define DD 1024
#define HH 16
#define DK 64
#define BL (BB*LL)              // 4096

typedef unsigned int u32;
typedef __nv_bfloat16 bf16;

// ---------------- scratch (device globals; no allocation allowed) ----------
__device__ __half g_P[(size_t)BB*HH*LL*LL];      // 256 MB probs (fp16)
__device__ bf16   g_xhi [BL*DD], g_xlo [BL*DD];
__device__ bf16   g_xshi[BL*DD], g_xslo[BL*DD];  // x * delta
__device__ bf16   g_Whi[4*DD*DD], g_Wlo[4*DD*DD]; // W hi/lo (q,k,v,o) [k][n]
__device__ bf16   g_Qhi[BL*DD], g_Qlo[BL*DD];
__device__ bf16   g_Khi[BL*DD], g_Klo[BL*DD];
__device__ __half g_V[BL*DD];                    // V (fp16 single)
__device__ bf16   g_Chi[BL*DD], g_Clo[BL*DD];    // context hi/lo

// ---------------- ptx helpers ----------------------------------------------
__device__ __forceinline__ u32 smem_u32(const void* p) {
    u32 a;
    asm("{ .reg .u64 t; cvta.to.shared.u64 t, %1; cvt.u32.u64 %0, t; }"
        : "=r"(a) : "l"(p));
    return a;
}

#define LDSM4(R0,R1,R2,R3,ADDR) \
    asm volatile("ldmatrix.sync.aligned.m8n8.x4.shared.b16 {%0,%1,%2,%3}, [%4];" \
        : "=r"(R0),"=r"(R1),"=r"(R2),"=r"(R3) : "r"(ADDR))
#define LDSM4T(R0,R1,R2,R3,ADDR) \
    asm volatile("ldmatrix.sync.aligned.m8n8.x4.trans.shared.b16 {%0,%1,%2,%3}, [%4];" \
        : "=r"(R0),"=r"(R1),"=r"(R2),"=r"(R3) : "r"(ADDR))

__device__ __forceinline__ void mma16816(float* c, const u32* a, const u32* b) {
    asm volatile(
        "mma.sync.aligned.m16n8k16.row.col.f32.bf16.bf16.f32 "
        "{%0,%1,%2,%3}, {%4,%5,%6,%7}, {%8,%9}, {%0,%1,%2,%3};"
        : "+f"(c[0]), "+f"(c[1]), "+f"(c[2]), "+f"(c[3])
        : "r"(a[0]), "r"(a[1]), "r"(a[2]), "r"(a[3]), "r"(b[0]), "r"(b[1]));
}

__device__ __forceinline__ void mma16816h(float* c, const u32* a, const u32* b) {
    asm volatile(
        "mma.sync.aligned.m16n8k16.row.col.f32.f16.f16.f32 "
        "{%0,%1,%2,%3}, {%4,%5,%6,%7}, {%8,%9}, {%0,%1,%2,%3};"
        : "+f"(c[0]), "+f"(c[1]), "+f"(c[2]), "+f"(c[3])
        : "r"(a[0]), "r"(a[1]), "r"(a[2]), "r"(a[3]), "r"(b[0]), "r"(b[1]));
}

#define CPA16(dst, src) \
    asm volatile("cp.async.cg.shared.global [%0], [%1], 16;" :: "r"(dst), "l"(src))
#define CPCOMMIT() asm volatile("cp.async.commit_group;" ::: "memory")
#define CPWAIT(n)  asm volatile("cp.async.wait_group %0;" :: "n"(n) : "memory")

// ---------------- async staging (swizzled) ----------------------------------
__device__ __forceinline__ void issue_A128(u32 dst, const bf16* A, size_t lda) {
#pragma unroll
    for (int i = 0; i < 4; i++) {
        int idx = threadIdx.x + (i << 8);
        int r = idx >> 3, c = idx & 7;
        int off = (r << 7) | (c << 4);
        CPA16(dst + (off ^ ((off >> 3) & 0x70)), A + (size_t)r * lda + (c << 3));
    }
}
__device__ __forceinline__ void issue_A256(u32 dst, const bf16* A, size_t lda) {
#pragma unroll
    for (int i = 0; i < 8; i++) {
        int idx = threadIdx.x + (i << 8);
        int r = idx >> 3, c = idx & 7;
        int off = (r << 7) | (c << 4);
        CPA16(dst + (off ^ ((off >> 3) & 0x70)), A + (size_t)r * lda + (c << 3));
    }
}
__device__ __forceinline__ void issue_B256(u32 dst, const bf16* B, size_t ldb) {
#pragma unroll
    for (int i = 0; i < 4; i++) {
        int idx = threadIdx.x + (i << 8);
        int r = idx >> 4, c = idx & 15;
        int off = (r << 8) | (c << 4);
        CPA16(dst + (off ^ ((off >> 4) & 0x70)), B + (size_t)r * ldb + (c << 3));
    }
}
__device__ __forceinline__ void issue_B64(u32 dst, const bf16* B, size_t ldb) {
#pragma unroll
    for (int i = 0; i < 2; i++) {
        int idx = threadIdx.x + (i << 8);
        int r = idx >> 3, c = idx & 7;
        int off = (r << 7) | (c << 4);
        CPA16(dst + (off ^ ((off >> 3) & 0x70)), B + (size_t)r * ldb + (c << 3));
    }
}

// ---------------- warp slab: 64x32 warp tile (projection GEMMs) ------------
template<int SW, int BMODE, int BPITCH>
__device__ __forceinline__ void warp_slab(
    u32 sAh, u32 sAl, u32 sBh, u32 sBl,
    int mwarp, int nwarp, int lane, float acc[4][4][4])
{
#pragma unroll
    for (int ks = 0; ks < 4; ks++) {
        const int k0 = ks << 4;
        u32 bh[4][2], bl[4][2], a[4][4];
#pragma unroll
        for (int nf = 0; nf < 2; nf++) {
            int off;
            if (BMODE == 0) {
                int kr = k0 + (lane & 15);
                int nc = nwarp + (nf << 4) + ((lane >> 4) << 3);
                off = kr * BPITCH + (nc << 1);
            } else {
                int nr = nwarp + (nf << 4) + (lane & 7) + ((lane >> 4) << 3);
                int kc = k0 + (((lane >> 3) & 1) << 3);
                off = (nr << 7) + (kc << 1);
            }
            int so = off ^ ((off >> SW) & 0x70);
            if (BMODE == 0) {
                LDSM4T(bh[nf*2][0], bh[nf*2][1], bh[nf*2+1][0], bh[nf*2+1][1], sBh + so);
                LDSM4T(bl[nf*2][0], bl[nf*2][1], bl[nf*2+1][0], bl[nf*2+1][1], sBl + so);
            } else {
                LDSM4(bh[nf*2][0], bh[nf*2][1], bh[nf*2+1][0], bh[nf*2+1][1], sBh + so);
                LDSM4(bl[nf*2][0], bl[nf*2][1], bl[nf*2+1][0], bl[nf*2+1][1], sBl + so);
            }
        }
        int arow = mwarp + (lane & 15);
        int acol = (k0 + ((lane >> 4) << 3)) << 1;
#pragma unroll
        for (int mf = 0; mf < 4; mf++) {
            int off = ((arow + (mf << 4)) << 7) + acol;
            int so = off ^ ((off >> 3) & 0x70);
            LDSM4(a[mf][0], a[mf][1], a[mf][2], a[mf][3], sAh + so);
        }
#pragma unroll
        for (int mf = 0; mf < 4; mf++)
#pragma unroll
            for (int nf = 0; nf < 4; nf++) {
                mma16816(acc[mf][nf], a[mf], bh[nf]);
                mma16816(acc[mf][nf], a[mf], bl[nf]);
            }
#pragma unroll
        for (int mf = 0; mf < 4; mf++) {
            int off = ((arow + (mf << 4)) << 7) + acol;
            int so = off ^ ((off >> 3) & 0x70);
            LDSM4(a[mf][0], a[mf][1], a[mf][2], a[mf][3], sAl + so);
        }
#pragma unroll
        for (int mf = 0; mf < 4; mf++)
#pragma unroll
            for (int nf = 0; nf < 4; nf++)
                mma16816(acc[mf][nf], a[mf], bh[nf]);
    }
}

// single-pass fp16 warp slab (context)
__device__ __forceinline__ void warp_slab_h(
    u32 sA, u32 sB, int mwarp, int nwarp, int lane, float acc[4][4][4])
{
#pragma unroll
    for (int ks = 0; ks < 4; ks++) {
        const int k0 = ks << 4;
        u32 b[4][2], a[4][4];
#pragma unroll
        for (int nf = 0; nf < 2; nf++) {
            int kr = k0 + (lane & 15);
            int nc = nwarp + (nf << 4) + ((lane >> 4) << 3);
            int off = (kr << 7) + (nc << 1);
            int so = off ^ ((off >> 3) & 0x70);
            LDSM4T(b[nf*2][0], b[nf*2][1], b[nf*2+1][0], b[nf*2+1][1], sB + so);
        }
        int arow = mwarp + (lane & 15);
        int acol = (k0 + ((lane >> 4) << 3)) << 1;
#pragma unroll
        for (int mf = 0; mf < 4; mf++) {
            int off = ((arow + (mf << 4)) << 7) + acol;
            int so = off ^ ((off >> 3) & 0x70);
            LDSM4(a[mf][0], a[mf][1], a[mf][2], a[mf][3], sA + so);
        }
#pragma unroll
        for (int mf = 0; mf < 4; mf++)
#pragma unroll
            for (int nf = 0; nf < 4; nf++)
                mma16816h(acc[mf][nf], a[mf], b[nf]);
    }
}

__device__ __forceinline__ void split_store2(bf16* H, bf16* L, float v0, float v1) {
    bf16 h0 = __float2bfloat16(v0), h1 = __float2bfloat16(v1);
    bf16 l0 = __float2bfloat16(v0 - __bfloat162float(h0));
    bf16 l1 = __float2bfloat16(v1 - __bfloat162float(h1));
    __nv_bfloat162 hp; hp.x = h0; hp.y = h1;
    __nv_bfloat162 lp; lp.x = l0; lp.y = l1;
    *(__nv_bfloat162*)H = hp;
    *(__nv_bfloat162*)L = lp;
}

__device__ __forceinline__ float fexp(float x) {
    x = fmaxf(x, -87.0f);
    float t = x * 1.4426950408889634f;
    int ei = __float2int_rn(t);
    float f = t - (float)ei;
    float p = 1.5403530e-4f;
    p = fmaf(p, f, 1.3333558e-3f);
    p = fmaf(p, f, 9.6181291e-3f);
    p = fmaf(p, f, 5.5504109e-2f);
    p = fmaf(p, f, 2.4022651e-1f);
    p = fmaf(p, f, 6.9314718e-1f);
    p = fmaf(p, f, 1.0f);
    return p * __int_as_float((ei + 127) << 23);
}

// ---------------- converters ------------------------------------------------
__global__ void __launch_bounds__(256) conv_x(
    const float* __restrict__ x, const float* __restrict__ dr,
    bf16* xh, bf16* xl, bf16* xsh, bf16* xsl)
{
    int i0 = blockIdx.x * 1024 + threadIdx.x;
#pragma unroll
    for (int k = 0; k < 4; k++) {
        int i = i0 + k * 256;
        float v = x[i];
        float d = dr[i >> 10];
        bf16 h = __float2bfloat16(v);
        xh[i] = h; xl[i] = __float2bfloat16(v - __bfloat162float(h));
        float vs = v * d;
        bf16 hs = __float2bfloat16(vs);
        xsh[i] = hs; xsl[i] = __float2bfloat16(vs - __bfloat162float(hs));
    }
}

__global__ void __launch_bounds__(256) conv_w4(
    const float* __restrict__ Wq, const float* __restrict__ Wk,
    const float* __restrict__ Wv, const float* __restrict__ Wo,
    bf16* __restrict__ H, bf16* __restrict__ L)
{
    int sel = blockIdx.y;
    const float* W = sel == 0 ? Wq : (sel == 1 ? Wk : (sel == 2 ? Wv : Wo));
    size_t base = (size_t)sel * DD * DD;
    int i0 = blockIdx.x * 1024 + threadIdx.x;
#pragma unroll
    for (int k = 0; k < 4; k++) {
        int i = i0 + k * 256;
        float v = W[i];
        bf16 h = __float2bfloat16(v);
        H[base + i] = h;
        L[base + i] = __float2bfloat16(v - __bfloat162float(h));
    }
}

// ---------------- 3-stage pipelined 128x128 GEMM mainloop (16 slabs) -------
#define PG_A   0
#define PG_AL  16384
#define PG_B   32768
#define PG_BL  49152
#define PG_STAGE 65536
#define PG_SMEM  (3 * PG_STAGE)

__device__ __forceinline__ void proj_issue(u32 st,
    const bf16* __restrict__ Ah, const bf16* __restrict__ Al,
    const bf16* __restrict__ Bh, const bf16* __restrict__ Bl, int s)
{
    issue_A128(st + PG_A,  Ah + s * 64, DD);
    issue_A128(st + PG_AL, Al + s * 64, DD);
    issue_B256(st + PG_B,  Bh + (size_t)s * 64 * DD, DD);
    issue_B256(st + PG_BL, Bl + (size_t)s * 64 * DD, DD);
    CPCOMMIT();
}

__device__ __forceinline__ void proj_mainloop(u32 sb,
    const bf16* __restrict__ Ah, const bf16* __restrict__ Al,
    const bf16* __restrict__ Bh, const bf16* __restrict__ Bl,
    int lane, int mwarp, int nwarp, float acc[4][4][4])
{
    proj_issue(sb + 0 * PG_STAGE, Ah, Al, Bh, Bl, 0);
    proj_issue(sb + 1 * PG_STAGE, Ah, Al, Bh, Bl, 1);
    for (int s = 0; s < 16; s++) {
        if (s < 15) { CPWAIT(1); } else { CPWAIT(0); }
        __syncthreads();
        if (s + 2 < 16)
            proj_issue(sb + ((s + 2) % 3) * PG_STAGE, Ah, Al, Bh, Bl, s + 2);
        u32 cur = sb + (s % 3) * PG_STAGE;
        warp_slab<4, 0, 256>(cur + PG_A, cur + PG_AL, cur + PG_B, cur + PG_BL,
                             mwarp, nwarp, lane, acc);
    }
}

// fused QKV projection
__global__ void __launch_bounds__(256) k_proj_qkv(
    const bf16* __restrict__ xh, const bf16* __restrict__ xl,
    const bf16* __restrict__ xsh, const bf16* __restrict__ xsl,
    const bf16* __restrict__ Whi, const bf16* __restrict__ Wlo,
    const float* __restrict__ bq, const float* __restrict__ bk,
    const float* __restrict__ bv,
    bf16* __restrict__ Qh, bf16* __restrict__ Ql,
    bf16* __restrict__ Kh, bf16* __restrict__ Kl,
    __half* __restrict__ Vp)
{
    extern __shared__ char sm[];
    u32 sb = smem_u32(sm);
    int ng = blockIdx.x << 7;
    int sel = ng >> 10, ncol = ng & 1023;
    int m0 = blockIdx.y << 7;
    int lane = threadIdx.x & 31, wid = threadIdx.x >> 5;
    int mwarp = (wid >> 2) << 6, nwarp = (wid & 3) << 5;

    const bf16* Ah = (sel == 2 ? xsh : xh) + (size_t)m0 * DD;
    const bf16* Al = (sel == 2 ? xsl : xl) + (size_t)m0 * DD;
    const bf16* Bh = Whi + (size_t)sel * DD * DD + ncol;
    const bf16* Bl = Wlo + (size_t)sel * DD * DD + ncol;
    const float* bias = sel == 0 ? bq : (sel == 1 ? bk : bv);
    bf16* Ohi = sel == 0 ? Qh : Kh;
    bf16* Olo = sel == 0 ? Ql : Kl;

    float acc[4][4][4];
#pragma unroll
    for (int i = 0; i < 4; i++)
#pragma unroll
        for (int j = 0; j < 4; j++)
#pragma unroll
            for (int k = 0; k < 4; k++) acc[i][j][k] = 0.0f;

    proj_mainloop(sb, Ah, Al, Bh, Bl, lane, mwarp, nwarp, acc);

    int g = lane >> 2, t = (lane & 3) << 1;
#pragma unroll
    for (int mf = 0; mf < 4; mf++)
#pragma unroll
        for (int half = 0; half < 2; half++) {
            int r = m0 + mwarp + (mf << 4) + g + (half << 3);
#pragma unroll
            for (int nf = 0; nf < 4; nf++) {
                int n = ncol + nwarp + (nf << 3) + t;
                float v0 = acc[mf][nf][half * 2 + 0] + bias[n];
                float v1 = acc[mf][nf][half * 2 + 1] + bias[n + 1];
                if (sel == 2) {
                    *(__half2*)(Vp + (size_t)r * DD + n) = __floats2half2_rn(v0, v1);
                } else {
                    split_store2(Ohi + (size_t)r * DD + n, Olo + (size_t)r * DD + n, v0, v1);
                }
            }
        }
}

// output projection: fp32 out + bias
__global__ void __launch_bounds__(256) k_proj_o(
    const bf16* __restrict__ Ch, const bf16* __restrict__ Cl,
    const bf16* __restrict__ Whi, const bf16* __restrict__ Wlo,
    const float* __restrict__ bias, float* __restrict__ Of)
{
    extern __shared__ char sm[];
    u32 sb = smem_u32(sm);
    int n0 = blockIdx.x << 7, m0 = blockIdx.y << 7;
    int lane = threadIdx.x & 31, wid = threadIdx.x >> 5;
    int mwarp = (wid >> 2) << 6, nwarp = (wid & 3) << 5;

    float acc[4][4][4];
#pragma unroll
    for (int i = 0; i < 4; i++)
#pragma unroll
        for (int j = 0; j < 4; j++)
#pragma unroll
            for (int k = 0; k < 4; k++) acc[i][j][k] = 0.0f;

    proj_mainloop(sb, Ch + (size_t)m0 * DD, Cl + (size_t)m0 * DD,
                  Whi + n0, Wlo + n0, lane, mwarp, nwarp, acc);

    int g = lane >> 2, t = (lane & 3) << 1;
#pragma unroll
    for (int mf = 0; mf < 4; mf++)
#pragma unroll
        for (int half = 0; half < 2; half++) {
            int r = m0 + mwarp + (mf << 4) + g + (half << 3);
#pragma unroll
            for (int nf = 0; nf < 4; nf++) {
                int n = n0 + nwarp + (nf << 3) + t;
                float2 o;
                o.x = acc[mf][nf][half * 2 + 0] + bias[n];
                o.y = acc[mf][nf][half * 2 + 1] + bias[n + 1];
                *(float2*)(Of + (size_t)r * DD + n) = o;
            }
        }
}

// ---------------- fused scores + softmax -> P fp16 --------------------------
// one block = 16 q-rows x full 2048 keys for one head. 512 threads (16 warps),
// warp w owns cols {s*256 + w*16 + [0,16)} over 8 slabs. Exact row max/sum.
#define FS_QHI 0
#define FS_QLO 2048
#define FS_RELB 4096
#define FS_RED  12288
#define FS_RMAX 13312
#define FS_RSUM 13376
#define FS_KS0  16384
#define FS_KS1  81920
#define FS_SMEM 147456
#define FS_PPITCH 4112

__device__ __forceinline__ void fs_issue_slab(u32 dst,
    const bf16* __restrict__ Kbh, const bf16* __restrict__ Kbl, int s, int tid)
{
#pragma unroll
    for (int i = 0; i < 4; i++) {
        int idx = tid + (i << 9);
        int r = idx >> 3, c = idx & 7;
        int off = (r << 7) | (c << 4);
        int swo = off ^ ((off >> 3) & 0x70);
        CPA16(dst + swo,         Kbh + (size_t)((s << 8) + r) * DD + (c << 3));
        CPA16(dst + 32768 + swo, Kbl + (size_t)((s << 8) + r) * DD + (c << 3));
    }
}

__global__ void __launch_bounds__(512) k_scores_softmax(
    const bf16* __restrict__ Qh, const bf16* __restrict__ Ql,
    const bf16* __restrict__ Kh, const bf16* __restrict__ Kl,
    const float* __restrict__ delta, __half* __restrict__ P)
{
    extern __shared__ char sm[];
    u32 sb = smem_u32(sm);
    int z = blockIdx.y, b = z >> 4;
    int h = z & 15;
    int m0 = blockIdx.x << 4;
    int tid = threadIdx.x, lane = tid & 31, w = tid >> 5;

    const bf16* Qbh = Qh + (size_t)(b * LL + m0) * DD + h * DK;
    const bf16* Qbl = Ql + (size_t)(b * LL + m0) * DD + h * DK;
    const bf16* Kbh = Kh + (size_t)(b * LL) * DD + h * DK;
    const bf16* Kbl = Kl + (size_t)(b * LL) * DD + h * DK;

    // stage Q strip (16x64 hi/lo) bundled with slab 0
    if (tid < 128) {
        int r = tid >> 3, c = tid & 7;
        int off = (r << 7) | (c << 4);
        int swo = off ^ ((off >> 3) & 0x70);
        CPA16(sb + FS_QHI + swo, Qbh + (size_t)r * DD + (c << 3));
        CPA16(sb + FS_QLO + swo, Qbl + (size_t)r * DD + (c << 3));
    }
    fs_issue_slab(sb + FS_KS0, Kbh, Kbl, 0, tid);
    CPCOMMIT();

    float* relb = (float*)(sm + FS_RELB);
    for (int i = tid; i < 2048; i += 512)
        relb[i] = logf(delta[b * LL + i] + 1e-6f);

    float acc[8][2][4];
#pragma unroll
    for (int s = 0; s < 8; s++)
#pragma unroll
        for (int t = 0; t < 2; t++)
#pragma unroll
            for (int r = 0; r < 4; r++) acc[s][t][r] = 0.0f;

    u32 a_hi[4][4];

#pragma unroll
    for (int s = 0; s < 8; s++) {
        CPWAIT(0);
        __syncthreads();
        if (s == 0) {
#pragma unroll
            for (int ks = 0; ks < 4; ks++) {
                int off = ((lane & 15) << 7) + (((ks << 4) + ((lane >> 4) << 3)) << 1);
                int swo = off ^ ((off >> 3) & 0x70);
                LDSM4(a_hi[ks][0], a_hi[ks][1], a_hi[ks][2], a_hi[ks][3],
                      sb + FS_QHI + swo);
            }
        }
        if (s + 1 < 8)
            fs_issue_slab(sb + (((s + 1) & 1) ? FS_KS1 : FS_KS0), Kbh, Kbl, s + 1, tid);
        if (s + 1 < 8) CPCOMMIT();
        u32 kbase = sb + ((s & 1) ? FS_KS1 : FS_KS0);
#pragma unroll
        for (int ks = 0; ks < 4; ks++) {
            int nr = (w << 4) + (lane & 7) + ((lane >> 4) << 3);
            int kc = (ks << 4) + (((lane >> 3) & 1) << 3);
            int off = (nr << 7) + (kc << 1);
            int swo = off ^ ((off >> 3) & 0x70);
            u32 bh[2][2], bl[2][2], al[4];
            LDSM4(bh[0][0], bh[0][1], bh[1][0], bh[1][1], kbase + swo);
            LDSM4(bl[0][0], bl[0][1], bl[1][0], bl[1][1], kbase + 32768 + swo);
            int aoff = ((lane & 15) << 7) + (((ks << 4) + ((lane >> 4) << 3)) << 1);
            int aswo = aoff ^ ((aoff >> 3) & 0x70);
            LDSM4(al[0], al[1], al[2], al[3], sb + FS_QLO + aswo);
#pragma unroll
            for (int t = 0; t < 2; t++) {
                mma16816(acc[s][t], a_hi[ks], bh[t]);
                mma16816(acc[s][t], a_hi[ks], bl[t]);
                mma16816(acc[s][t], al,       bh[t]);
            }
        }
    }

    // ---- bias terms + row max ----
    int g = lane >> 2, cq = (lane & 3) << 1;
    int mA = m0 + g, mB = m0 + g + 8;
    float mx0 = -1e30f, mx1 = -1e30f;
#pragma unroll
    for (int s = 0; s < 8; s++)
#pragma unroll
        for (int t = 0; t < 2; t++) {
            int n = (s << 8) + (w << 4) + (t << 3) + cq;
            float rb0 = relb[n], rb1 = relb[n + 1];
            acc[s][t][0] = acc[s][t][0] * 0.125f - 0.1f * fabsf((float)(mA - n))     + rb0;
            acc[s][t][1] = acc[s][t][1] * 0.125f - 0.1f * fabsf((float)(mA - n - 1)) + rb1;
            acc[s][t][2] = acc[s][t][2] * 0.125f - 0.1f * fabsf((float)(mB - n))     + rb0;
            acc[s][t][3] = acc[s][t][3] * 0.125f - 0.1f * fabsf((float)(mB - n - 1)) + rb1;
            mx0 = fmaxf(mx0, fmaxf(acc[s][t][0], acc[s][t][1]));
            mx1 = fmaxf(mx1, fmaxf(acc[s][t][2], acc[s][t][3]));
        }
    mx0 = fmaxf(mx0, __shfl_xor_sync(0xffffffffu, mx0, 1));
    mx0 = fmaxf(mx0, __shfl_xor_sync(0xffffffffu, mx0, 2));
    mx1 = fmaxf(mx1, __shfl_xor_sync(0xffffffffu, mx1, 1));
    mx1 = fmaxf(mx1, __shfl_xor_sync(0xffffffffu, mx1, 2));
    float* red  = (float*)(sm + FS_RED);
    float* rmax = (float*)(sm + FS_RMAX);
    float* rsum = (float*)(sm + FS_RSUM);
    if ((lane & 3) == 0) {
        red[w * 16 + g]     = mx0;
        red[w * 16 + g + 8] = mx1;
    }
    __syncthreads();
    if (tid < 16) {
        float m = -1e30f;
#pragma unroll
        for (int w2 = 0; w2 < 16; w2++) m = fmaxf(m, red[w2 * 16 + tid]);
        rmax[tid] = m;
    }
    __syncthreads();

    // ---- exp + row sum ----
    float rm0 = rmax[g], rm1 = rmax[g + 8];
    float sm0 = 0.0f, sm1 = 0.0f;
#pragma unroll
    for (int s = 0; s < 8; s++)
#pragma unroll
        for (int t = 0; t < 2; t++) {
            acc[s][t][0] = fexp(acc[s][t][0] - rm0);
            acc[s][t][1] = fexp(acc[s][t][1] - rm0);
            acc[s][t][2] = fexp(acc[s][t][2] - rm1);
            acc[s][t][3] = fexp(acc[s][t][3] - rm1);
            sm0 += acc[s][t][0] + acc[s][t][1];
            sm1 += acc[s][t][2] + acc[s][t][3];
        }
    sm0 += __shfl_xor_sync(0xffffffffu, sm0, 1);
    sm0 += __shfl_xor_sync(0xffffffffu, sm0, 2);
    sm1 += __shfl_xor_sync(0xffffffffu, sm1, 1);
    sm1 += __shfl_xor_sync(0xffffffffu, sm1, 2);
    if ((lane & 3) == 0) {
        red[w * 16 + g]     = sm0;
        red[w * 16 + g + 8] = sm1;
    }
    __syncthreads();
    if (tid < 16) {
        float s2 = 0.0f;
#pragma unroll
        for (int w2 = 0; w2 < 16; w2++) s2 += red[w2 * 16 + tid];
        rsum[tid] = s2;
    }
    __syncthreads();

    // ---- normalize, stage fp16 P tile, coalesced write ----
    float inv0 = 1.0f / rsum[g], inv1 = 1.0f / rsum[g + 8];
#pragma unroll
    for (int s = 0; s < 8; s++)
#pragma unroll
        for (int t = 0; t < 2; t++) {
            int n = (s << 8) + (w << 4) + (t << 3) + cq;
            __half2 p0 = __floats2half2_rn(acc[s][t][0] * inv0, acc[s][t][1] * inv0);
            __half2 p1 = __floats2half2_rn(acc[s][t][2] * inv1, acc[s][t][3] * inv1);
            *(__half2*)(sm + FS_KS0 + g * FS_PPITCH        + (n << 1)) = p0;
            *(__half2*)(sm + FS_KS0 + (g + 8) * FS_PPITCH  + (n << 1)) = p1;
        }
    __syncthreads();
    char* Pg = (char*)(P + ((size_t)z * LL + m0) * LL);
#pragma unroll
    for (int i = 0; i < 8; i++) {
        int idx = tid + (i << 9);
        int row = idx >> 8, chunk = idx & 255;
        uint4 v = *(uint4*)(sm + FS_KS0 + row * FS_PPITCH + (chunk << 4));
        *(uint4*)(Pg + (size_t)row * 4096 + (chunk << 4)) = v;
    }
}

// ---------------- mean over heads -> out[BL*DD ...] -------------------------
__global__ void __launch_bounds__(256) k_mean(
    const __half* __restrict__ P, float* __restrict__ outm)
{
    int bq = blockIdx.x;
    int b = bq >> 11, q = bq & 2047;
    int tid = threadIdx.x;
    float acc0[4] = {0, 0, 0, 0}, acc1[4] = {0, 0, 0, 0};
    for (int h = 0; h < HH; h++) {
        const __half* row = P + ((size_t)(b * HH + h) * LL + q) * LL;
        union { uint2 u; __half2 h2[2]; } v0, v1;
        v0.u = *(const uint2*)(row + (tid << 2));
        v1.u = *(const uint2*)(row + (tid << 2) + 1024);
        float2 a = __half22float2(v0.h2[0]), bb = __half22float2(v0.h2[1]);
        float2 c = __half22float2(v1.h2[0]), d = __half22float2(v1.h2[1]);
        acc0[0] += a.x; acc0[1] += a.y; acc0[2] += bb.x; acc0[3] += bb.y;
        acc1[0] += c.x; acc1[1] += c.y; acc1[2] += d.x;  acc1[3] += d.y;
    }
    float* o = outm + ((size_t)bq * LL);
    float4 o0, o1;
    o0.x = acc0[0] * 0.0625f; o0.y = acc0[1] * 0.0625f;
    o0.z = acc0[2] * 0.0625f; o0.w = acc0[3] * 0.0625f;
    o1.x = acc1[0] * 0.0625f; o1.y = acc1[1] * 0.0625f;
    o1.z = acc1[2] * 0.0625f; o1.w = acc1[3] * 0.0625f;
    *(float4*)(o + (tid << 2))        = o0;
    *(float4*)(o + (tid << 2) + 1024) = o1;
}

// ---------------- context: ctx = P @ V (fp16 1-pass) ------------------------
#define C_A   0
#define C_B   32768
#define C_STAGE 40960
#define C_SMEM  81920

__device__ __forceinline__ void ctx_issue(u32 st, const __half* Pb,
                                          const __half* Vb, int s)
{
    issue_A256(st + C_A, (const bf16*)(Pb + s * 64), LL);
    issue_B64 (st + C_B, (const bf16*)(Vb + (size_t)s * 64 * DD), DD);
    CPCOMMIT();
}

__global__ void __launch_bounds__(256) k_context(
    const __half* __restrict__ P, const __half* __restrict__ V,
    bf16* __restrict__ Chi, bf16* __restrict__ Clo)
{
    extern __shared__ char sm[];
    u32 sb = smem_u32(sm);
    int z = blockIdx.y, b = z >> 4, h = z & 15;
    int m0 = blockIdx.x << 8;
    int lane = threadIdx.x & 31, wid = threadIdx.x >> 5;
    int mwarp = (wid >> 1) << 6, nwarp = (wid & 1) << 5;

    float acc[4][4][4];
#pragma unroll
    for (int i = 0; i < 4; i++)
#pragma unroll
        for (int j = 0; j < 4; j++)
#pragma unroll
            for (int k = 0; k < 4; k++) acc[i][j][k] = 0.0f;

    const __half* Pb = P + (size_t)z * LL * LL + (size_t)m0 * LL;
    const __half* Vb = V + (size_t)b * LL * DD + h * DK;

    ctx_issue(sb, Pb, Vb, 0);
    for (int s = 0; s < LL / 64; s++) {
        CPWAIT(0);
        __syncthreads();
        if (s + 1 < LL / 64)
            ctx_issue(sb + ((s + 1) & 1) * C_STAGE, Pb, Vb, s + 1);
        u32 cur = sb + (s & 1) * C_STAGE;
        warp_slab_h(cur + C_A, cur + C_B, mwarp, nwarp, lane, acc);
    }

    int g = lane >> 2, t = (lane & 3) << 1;
#pragma unroll
    for (int mf = 0; mf < 4; mf++)
#pragma unroll
        for (int half = 0; half < 2; half++) {
            int r = m0 + mwarp + (mf << 4) + g + (half << 3);
            size_t rb = (size_t)(b * LL + r) * DD + h * DK;
#pragma unroll
            for (int nf = 0; nf < 4; nf++) {
                int n = nwarp + (nf << 3) + t;
                split_store2(Chi + rb + n, Clo + rb + n,
                             acc[mf][nf][half * 2 + 0], acc[mf][nf][half * 2 + 1]);
            }
        }
}

// ---------------- launch ----------------------------------------------------
extern "C" void kernel_launch(void* const* d_in, const int* in_sizes, int n_in,
                              void* d_out, int out_size)
{
    const float* x   = (const float*)d_in[0];
    const float* dr  = (const float*)d_in[1];
    const float* Wq  = (const float*)d_in[2];
    const float* bq  = (const float*)d_in[3];
    const float* Wk  = (const float*)d_in[4];
    const float* bk  = (const float*)d_in[5];
    const float* Wv  = (const float*)d_in[6];
    const float* bv  = (const float*)d_in[7];
    const float* Wo  = (const float*)d_in[8];
    const float* bo  = (const float*)d_in[9];
    float* out = (float*)d_out;

    __half *pP, *pV;
    bf16 *pxhi, *pxlo, *pxshi, *pxslo, *pWhi, *pWlo;
    bf16 *pQhi, *pQlo, *pKhi, *pKlo, *pChi, *pClo;
    cudaGetSymbolAddress((void**)&pP,    g_P);
    cudaGetSymbolAddress((void**)&pV,    g_V);
    cudaGetSymbolAddress((void**)&pxhi,  g_xhi);
    cudaGetSymbolAddress((void**)&pxlo,  g_xlo);
    cudaGetSymbolAddress((void**)&pxshi, g_xshi);
    cudaGetSymbolAddress((void**)&pxslo, g_xslo);
    cudaGetSymbolAddress((void**)&pWhi,  g_Whi);
    cudaGetSymbolAddress((void**)&pWlo,  g_Wlo);
    cudaGetSymbolAddress((void**)&pQhi,  g_Qhi);
    cudaGetSymbolAddress((void**)&pQlo,  g_Qlo);
    cudaGetSymbolAddress((void**)&pKhi,  g_Khi);
    cudaGetSymbolAddress((void**)&pKlo,  g_Klo);
    cudaGetSymbolAddress((void**)&pChi,  g_Chi);
    cudaGetSymbolAddress((void**)&pClo,  g_Clo);

    cudaFuncSetAttribute(k_proj_qkv, cudaFuncAttributeMaxDynamicSharedMemorySize, PG_SMEM);
    cudaFuncSetAttribute(k_proj_o,   cudaFuncAttributeMaxDynamicSharedMemorySize, PG_SMEM);
    cudaFuncSetAttribute(k_scores_softmax, cudaFuncAttributeMaxDynamicSharedMemorySize, FS_SMEM);
    cudaFuncSetAttribute(k_context,  cudaFuncAttributeMaxDynamicSharedMemorySize, C_SMEM);

    // converters
    conv_x<<<BL, 256>>>(x, dr, pxhi, pxlo, pxshi, pxslo);
    dim3 gw(1024, 4);
    conv_w4<<<gw, 256>>>(Wq, Wk, Wv, Wo, pWhi, pWlo);

    // fused QKV projection (3-stage pipelined HMMA)
    dim3 gqkv(3 * DD / 128, BL / 128);   // (24, 32)
    k_proj_qkv<<<gqkv, 256, PG_SMEM>>>(pxhi, pxlo, pxshi, pxslo, pWhi, pWlo,
                                       bq, bk, bv,
                                       pQhi, pQlo, pKhi, pKlo, pV);

    // fused scores + softmax -> P fp16 (no S buffer)
    dim3 gfs(LL / 16, BB * HH);          // (128, 32)
    k_scores_softmax<<<gfs, 512, FS_SMEM>>>(pQhi, pQlo, pKhi, pKlo, dr, pP);

    // mean over heads
    bool write_mean = (out_size >= (BL * DD + BB * LL * LL));
    if (write_mean)
        k_mean<<<BL, 256>>>(pP, out + (size_t)BL * DD);

    // context (fp16 single-pass, 2-stage single-sync pipelined)
    dim3 gctx(LL / 256, BB * HH);        // (8, 32)
    k_context<<<gctx, 256, C_SMEM>>>(pP, pV, pChi, pClo);

    // output projection (fp32 out + bias)
    dim3 go(DD / 128, BL / 128);         // (8, 32)
    k_proj_o<<<go, 256, PG_SMEM>>>(pChi, pClo, pWhi + 3 * DD * DD, pWlo + 3 * DD * DD,
                                   bo, out);
}